// round 12
// baseline (speedup 1.0000x reference)
#include <cuda_runtime.h>
#include <cuda_bf16.h>
#include <math.h>
#include <stdint.h>

#define N_   8
#define CI1  32
#define CO   64
#define T_   8
#define H_   256
#define W_   256
#define HW   (H_*W_)
#define BN_EPS 1e-5f

// flat-tau chunking: tau = pair*25 + tap, chunk c covers tau in [32c, 32c+32)
#define NCH1 13
#define NCH2 25

// ================= device scratch =================
__device__ float d_y1[(size_t)N_ * CO * HW];
__device__ float d_gates[2][N_][5][CO];
// bf16 hi/lo weight tiles: [n][chunk][part(hi,lo)][8KB], row=co(64), col=k(64), SW128
__device__ uint4 d_wka1[(size_t)N_ * NCH1 * 2 * 8192 / 16];
__device__ uint4 d_wka2[(size_t)N_ * NCH2 * 2 * 8192 / 16];
// plain float weights for fallback path: [n][ci][tap][co]
__device__ float d_wkf1[(size_t)N_ * CI1 * 25 * CO];
__device__ float d_wkf2[(size_t)N_ * CO  * 25 * CO];
__device__ float d_psum[CO * N_];
__device__ float d_psq [CO * N_];
__device__ float d_bn[2][2][CO];

// ================= common helpers =================
__device__ __forceinline__ uint32_t smem_u32(const void* p) {
    uint32_t a;
    asm("{ .reg .u64 t; cvta.to.shared.u64 t, %1; cvt.u32.u64 %0, t; }" : "=r"(a) : "l"(p));
    return a;
}
#define SWZ128(o) ((o) ^ (((o) >> 3) & 0x70))

__device__ __forceinline__ unsigned long long pk2(float lo, float hi) {
    unsigned long long r;
    asm("mov.b64 %0, {%1, %2};" : "=l"(r)
        : "r"(__float_as_uint(lo)), "r"(__float_as_uint(hi)));
    return r;
}
__device__ __forceinline__ void fma2(unsigned long long& d,
                                     unsigned long long a, unsigned long long b) {
    asm("fma.rn.f32x2 %0, %1, %2, %0;" : "+l"(d) : "l"(a), "l"(b));
}
__device__ __forceinline__ float2 upk2(unsigned long long v) {
    unsigned int lo, hi;
    asm("mov.b64 {%0, %1}, %2;" : "=r"(lo), "=r"(hi) : "l"(v));
    return make_float2(__uint_as_float(lo), __uint_as_float(hi));
}

// ================= tcgen05 PTX (guarded) =================
#define MBARRIER_INIT(addr, cnt) \
    asm volatile("mbarrier.init.shared.b64 [%0], %1;" :: "r"(addr), "r"(cnt) : "memory")
#define MBARRIER_INVAL(addr) \
    asm volatile("mbarrier.inval.shared.b64 [%0];" :: "r"(addr) : "memory")
#define MBARRIER_WAIT_PARITY(addr, par) do {                                  \
    uint32_t _m = (addr); uint32_t _p = (par); uint32_t _done;                \
    asm volatile("{\n\t.reg .pred p;\n\t"                                     \
        "mbarrier.try_wait.parity.acquire.cta.shared::cta.b64 p, [%1], %2;\n\t" \
        "selp.b32 %0, 1, 0, p;\n\t}"                                          \
        : "=r"(_done) : "r"(_m), "r"(_p) : "memory");                         \
    if (!_done) {                                                             \
        asm volatile("{\n\t.reg .pred P1;\n\t"                                \
            "WL_%=:\n\t"                                                      \
            "mbarrier.try_wait.parity.acquire.cta.shared::cta.b64 P1, [%0], %1, 0x989680;\n\t" \
            "@P1 bra.uni WD_%=;\n\t"                                          \
            "bra.uni WL_%=;\n\t"                                              \
            "WD_%=:\n\t}" :: "r"(_m), "r"(_p) : "memory");                    \
    }                                                                         \
} while (0)

#define TCGEN05_ALLOC(sm, n) \
    asm volatile("tcgen05.alloc.cta_group::1.sync.aligned.shared::cta.b32 [%0], %1;" \
        :: "r"(sm), "r"((uint32_t)(n)) : "memory")
#define TCGEN05_DEALLOC(tm, n) \
    asm volatile("tcgen05.dealloc.cta_group::1.sync.aligned.b32 %0, %1;" :: "r"(tm), "r"((uint32_t)(n)))
#define TCGEN05_RELINQ() \
    asm volatile("tcgen05.relinquish_alloc_permit.cta_group::1.sync.aligned;")
#define TCGEN05_COMMIT(mb) \
    asm volatile("tcgen05.commit.cta_group::1.mbarrier::arrive::one.shared::cluster.b64 [%0];" \
        :: "r"(mb) : "memory")
#define TCGEN05_FENCE_AFTER()  asm volatile("tcgen05.fence::after_thread_sync;" ::: "memory")
#define TCGEN05_WAIT_LD()      asm volatile("tcgen05.wait::ld.sync.aligned;" ::: "memory")
#define FENCE_ASYNC() asm volatile("fence.proxy.async.shared::cta;" ::: "memory")

#define TCGEN05_LD_X32(r, a)                                                  \
    asm volatile("tcgen05.ld.sync.aligned.32x32b.x32.b32 "                    \
        "{%0, %1, %2, %3, %4, %5, %6, %7, %8, %9, %10, %11, %12, %13, %14, %15, " \
        " %16, %17, %18, %19, %20, %21, %22, %23, %24, %25, %26, %27, %28, %29, %30, %31}, [%32];" \
        : "=r"((r)[0]),  "=r"((r)[1]),  "=r"((r)[2]),  "=r"((r)[3]),          \
          "=r"((r)[4]),  "=r"((r)[5]),  "=r"((r)[6]),  "=r"((r)[7]),          \
          "=r"((r)[8]),  "=r"((r)[9]),  "=r"((r)[10]), "=r"((r)[11]),         \
          "=r"((r)[12]), "=r"((r)[13]), "=r"((r)[14]), "=r"((r)[15]),         \
          "=r"((r)[16]), "=r"((r)[17]), "=r"((r)[18]), "=r"((r)[19]),         \
          "=r"((r)[20]), "=r"((r)[21]), "=r"((r)[22]), "=r"((r)[23]),         \
          "=r"((r)[24]), "=r"((r)[25]), "=r"((r)[26]), "=r"((r)[27]),         \
          "=r"((r)[28]), "=r"((r)[29]), "=r"((r)[30]), "=r"((r)[31])          \
        : "r"(a))

// K-major SW128 descriptor (Blackwell version=1): LBO=1, SBO=64
static __device__ __forceinline__ uint64_t desc_k_sw128(uint32_t addr) {
    return ((uint64_t)2 << 61) | ((uint64_t)1 << 46) | ((uint64_t)64 << 32) |
           ((uint64_t)1 << 16) | ((uint64_t)(addr >> 4) & 0x3FFF);
}
// idesc: kind::f16, D=F32(bit4), A=BF16(bit7), B=BF16(bit10), N=64 (8<<17), M=128 (8<<24)
#define MMA_IDESC ((1u << 4) | (1u << 7) | (1u << 10) | (8u << 17) | (8u << 24))

// ================= SMEM layout (tensor path) =================
// ctrl 1KB | stage ring 3 x 1320 uint2 (31680B) | W 16KB | A 64KB = 112 KB, 2 CTAs/SM
#define STG_OFF 1024
#define BW_OFF  32768
#define A_OFF   49152
#define SMEM_SZ 114688

// ================= gates =================
__global__ void gate_kernel(const float* __restrict__ t,
                            const float* __restrict__ gw1, const float* __restrict__ gb1,
                            const float* __restrict__ gw2, const float* __restrict__ gb2) {
    int l = blockIdx.x;
    const float* gw = l ? gw2 : gw1;
    const float* gb = l ? gb2 : gb1;
    int n = threadIdx.x / CO;
    int o = threadIdx.x % CO;
    float tt[T_];
#pragma unroll
    for (int k = 0; k < T_; k++) tt[k] = t[n * T_ + k];
    float lg[5];
    float m = -1e30f;
#pragma unroll
    for (int e = 0; e < 5; e++) {
        int row = e * CO + o;
        float s = gb[row];
#pragma unroll
        for (int k = 0; k < T_; k++) s = fmaf(tt[k], gw[row * T_ + k], s);
        lg[e] = s;
        m = fmaxf(m, s);
    }
    float sum = 0.f;
#pragma unroll
    for (int e = 0; e < 5; e++) { lg[e] = expf(lg[e] - m); sum += lg[e]; }
    float inv = 1.f / sum;
#pragma unroll
    for (int e = 0; e < 5; e++) d_gates[l][n][e][o] = lg[e] * inv;
}

// ================= build per-sample mixed kernels =================
__global__ void build_w(int layer, int Ci, int nchunk,
                        const float* __restrict__ w5, const float* __restrict__ w3,
                        const float* __restrict__ w1, const float* __restrict__ a3,
                        const float* __restrict__ a5,
                        uint8_t* __restrict__ wka, float* __restrict__ wkf) {
    int NPAIR = Ci / 2;
    int idx = blockIdx.x * blockDim.x + threadIdx.x;
    int total = N_ * CO * NPAIR;
    if (idx >= total) return;
    int pair = idx % NPAIR;
    int o = (idx / NPAIR) % CO;
    int n = idx / (NPAIR * CO);
    float g0 = d_gates[layer][n][0][o];
    float g1 = d_gates[layer][n][1][o];
    float g2 = d_gates[layer][n][2][o];
    float g3 = d_gates[layer][n][3][o];
    float g4 = d_gates[layer][n][4][o];
#pragma unroll
    for (int ci_l = 0; ci_l < 2; ci_l++) {
        int i = pair * 2 + ci_l;
        int oi = o * Ci + i;
        for (int tap = 0; tap < 25; tap++) {
            int dy = tap / 5, dx = tap % 5;
            float v = g0 * w5[oi * 25 + tap] + g4 * a5[oi] * (1.f / 125.f);
            if (dy >= 1 && dy <= 3 && dx >= 1 && dx <= 3) {
                v += g1 * w3[oi * 9 + (dy - 1) * 3 + (dx - 1)];
                v += g3 * a3[oi] * (1.f / 27.f);
            }
            if (dy == 2 && dx == 2) v += g2 * w1[oi];
            wkf[(((size_t)(n * Ci + i) * 25 + tap) * CO + o)] = v;

            int tau = pair * 25 + tap;
            int c = tau >> 5;
            int k = (tau & 31) * 2 + ci_l;
            __nv_bfloat16 hi = __float2bfloat16(v);
            float lo_f = v - __bfloat162float(hi);
            __nv_bfloat16 lo = __float2bfloat16(lo_f);
            uint32_t off = SWZ128((uint32_t)(o * 128 + k * 2));
            size_t base = ((size_t)(n * nchunk + c) * 2) * 8192;
            *reinterpret_cast<__nv_bfloat16*>(wka + base + off) = hi;
            *reinterpret_cast<__nv_bfloat16*>(wka + base + 8192 + off) = lo;
        }
    }
}

// ================= zero stats accumulators =================
__global__ void zero_stats() {
    int i = threadIdx.x;
    d_psum[i] = 0.f;
    d_psq[i]  = 0.f;
}

// ================= conv kernel (256 threads, 2 CTAs/SM) =================
// Half-chunk column ping-pong: half g covers kslots [16h,16h+16) of chunk c=g>>1.
// MMA(g) reads A/W cols[h]; fill(g+1) writes the other column half concurrently.
template <int CI>
__global__ void __launch_bounds__(256, 2) conv_mma(const float* __restrict__ in,
                                                   const uint4* __restrict__ wka,
                                                   const float* __restrict__ wkf,
                                                   float* __restrict__ out,
                                                   int bnLayer) {
    extern __shared__ char smem[];
    constexpr int NPAIR = CI / 2;
    constexpr int TAU = NPAIR * 25;
    constexpr int NCHUNK = (TAU + 31) / 32;
    constexpr int NHALF = TAU / 16;          // 25 (L1) / 50 (L2), exact
    int tid = threadIdx.x;
    int n = blockIdx.x >> 8;
    int y = blockIdx.x & 255;
    const bool bn = (bnLayer >= 0);
    const float* inN = in + (size_t)n * CI * HW;

#if defined(__CUDA_ARCH_FEAT_SM103_ALL) || defined(__CUDA_ARCH_FEAT_SM100_ALL)
    // ================== tcgen05 tensor-core path ==================
    uint32_t sb = smem_u32(smem);
    int wid = tid >> 5;
    int lid = tid & 31;
    uint32_t mbar[2] = {sb + 8, sb + 16};

    if (wid == 0) {
        TCGEN05_ALLOC(sb, 128);
        TCGEN05_RELINQ();          // free permit so twin CTA can allocate
    }
    if (tid == 0) { MBARRIER_INIT(mbar[0], 1); MBARRIER_INIT(mbar[1], 1); }
    __syncthreads();
    uint32_t tmem;
    asm volatile("ld.shared.b32 %0, [%1];" : "=r"(tmem) : "r"(sb));

    // ---- per-thread A-fill mapping: kg2 = tid>>6 (0..3), x0 = tid&63, 4 its ----
    const int kg2 = tid >> 6;
    const int x0 = tid & 63;
    const uint32_t sts_b[2] = {
        SWZ128((uint32_t)(x0 * 128 + kg2 * 16)),
        SWZ128((uint32_t)(x0 * 128 + 64 + kg2 * 16))
    };
    // W half-copy offset (LDG offset == STS offset, image is pre-swizzled)
    const uint32_t woff[2] = {
        SWZ128((uint32_t)((tid >> 2) * 128 + (tid & 3) * 16)),
        SWZ128((uint32_t)((tid >> 2) * 128 + 64 + (tid & 3) * 16))
    };

    // ---- stage element offsets (per-thread, pair-invariant) ----
    uint32_t sofs[6];
    uint32_t smask = 0;
#pragma unroll
    for (int i = 0; i < 6; i++) {
        int p = tid + i * 256;
        int c = p % 264, r = p / 264;
        int srcy = y + r - 2, g = c - 2;
        bool v = (p < 1320) && ((unsigned)srcy < (unsigned)H_) && ((unsigned)g < (unsigned)W_);
        sofs[i] = v ? (uint32_t)(srcy * W_ + g) : 0u;
        if (v) smask |= 1u << i;
    }

    uint2* stage = reinterpret_cast<uint2*>(smem + STG_OFF);   // ring: 3 x 1320 uint2

    auto loadPair = [&](int q, uint2* u) {
        const float* base = inN + (size_t)q * 2 * HW;
        float s0 = 1.f, b0 = 0.f, s1 = 1.f, b1 = 0.f;
        if (bn) {
            s0 = d_bn[bnLayer][0][2 * q];     b0 = d_bn[bnLayer][1][2 * q];
            s1 = d_bn[bnLayer][0][2 * q + 1]; b1 = d_bn[bnLayer][1][2 * q + 1];
        }
#pragma unroll
        for (int i = 0; i < 6; i++) {
            float va = 0.f, vb = 0.f;
            if (smask >> i & 1) { va = base[sofs[i]]; vb = base[HW + sofs[i]]; }
            if (bn) {
                va = fmaxf(fmaf(va, s0, b0), 0.f);
                vb = fmaxf(fmaf(vb, s1, b1), 0.f);
            }
            uint32_t ua = __float_as_uint(va), ub = __float_as_uint(vb);
            float ha = __uint_as_float(ua & 0xFFFF0000u);
            float hb = __uint_as_float(ub & 0xFFFF0000u);
            u[i].x = __byte_perm(ua, ub, 0x7632);                        // hi pair
            u[i].y = __byte_perm(__float_as_uint(va - ha),
                                 __float_as_uint(vb - hb), 0x7632);      // lo pair
        }
    };
    auto storePair = [&](int q, const uint2* u) {
        uint2* s = stage + (q % 3) * 1320;
#pragma unroll
        for (int i = 0; i < 6; i++) {
            int p = tid + i * 256;
            if (i < 5 || p < 1320) s[p] = u[i];
        }
    };

    // ---- prologue: pairs 0,1 ----
    {
        uint2 u[6];
        loadPair(0, u); storePair(0, u);
        loadPair(1, u); storePair(1, u);
    }
    __syncthreads();

    const uint4* wkN = wka + (size_t)n * NCHUNK * 1024;   // 16KB (1024 uint4) per chunk
    int ph[2] = {0, 0};

    for (int g = 0; g < NHALF; g++) {
        int c = g >> 1, h = g & 1;

        // ---- phase 0: prefetch W half (hi+lo) + stage pairs (h==0) ----
        const uint8_t* wchunk = reinterpret_cast<const uint8_t*>(wkN + (size_t)c * 1024);
        uint4 wHi = *reinterpret_cast<const uint4*>(wchunk + woff[h]);
        uint4 wLo = *reinterpret_cast<const uint4*>(wchunk + 8192 + woff[h]);

        int nNew = 0, pNew = 0;
        uint2 u0[6], u1[6];
        if (h == 0 && c + 1 < NCHUNK) {
            int phiC = (32 * c + 31) / 25;       if (phiC > NPAIR - 1) phiC = NPAIR - 1;
            int phiN = (32 * c + 63) / 25;       if (phiN > NPAIR - 1) phiN = NPAIR - 1;
            nNew = phiN - phiC;                  // 0..2
            pNew = phiC + 1;
            if (nNew >= 1) loadPair(pNew, u0);
            if (nNew >= 2) loadPair(pNew + 1, u1);
        }

        // ---- phase 1: wait for MMA(g-2) (same column half) ----
        if (g >= 2) { MBARRIER_WAIT_PARITY(mbar[h], ph[h]); ph[h] ^= 1; }

        // ---- phase 2a: A-fill of column half h (4 kgroups x 4 its) ----
        {
            int tau0 = 32 * c + 16 * h + kg2 * 4;
            uint32_t off[4];
#pragma unroll
            for (int j = 0; j < 4; j++) {
                int t = tau0 + j;
                int pr = t / 25;
                int tap = t - 25 * pr;
                off[j] = (uint32_t)((pr % 3) * 1320 + (tap / 5) * 264 + x0 + (tap % 5));
            }
            char* Ab = smem + A_OFF;
            uint32_t so0 = sts_b[h];
#pragma unroll
            for (int it = 0; it < 4; it++) {
                uint2 v0 = stage[off[0] + it * 64];
                uint2 v1 = stage[off[1] + it * 64];
                uint2 v2 = stage[off[2] + it * 64];
                uint2 v3 = stage[off[3] + it * 64];
                uint32_t so = so0 + it * 8192;
                *reinterpret_cast<uint4*>(Ab + so) = make_uint4(v0.x, v1.x, v2.x, v3.x);
                *reinterpret_cast<uint4*>(Ab + 32768 + so) = make_uint4(v0.y, v1.y, v2.y, v3.y);
            }
        }
        // ---- phase 2b: store W half ----
        {
            uint8_t* wb = reinterpret_cast<uint8_t*>(smem + BW_OFF);
            *reinterpret_cast<uint4*>(wb + woff[h]) = wHi;
            *reinterpret_cast<uint4*>(wb + 8192 + woff[h]) = wLo;
        }
        // ---- phase 3: stage stores (h==0 only; sync guards ring overwrite) ----
        if (nNew) {
            __syncthreads();
            if (nNew >= 1) storePair(pNew, u0);
            if (nNew >= 2) storePair(pNew + 1, u1);
        }
        FENCE_ASYNC();
        __syncthreads();

        // ---- phase 4: issue 12 MMAs for this half ----
        if (tid == 0) {
            uint32_t aBase = sb + A_OFF;
            uint32_t bBase = sb + BW_OFF;
#pragma unroll
            for (int part = 0; part < 3; part++) {
                uint32_t apart = (part == 1) ? 32768u : 0u;   // A lo for part1
                uint32_t bpart = (part == 2) ? 8192u  : 0u;   // B lo for part2
                uint64_t bd = desc_k_sw128(bBase + bpart);
#pragma unroll
                for (int xblk = 0; xblk < 2; xblk++) {
                    uint64_t ad = desc_k_sw128(aBase + apart + xblk * 16384);
                    uint32_t dt = tmem + xblk * 64;
#pragma unroll
                    for (int kk = 0; kk < 2; kk++) {
                        int k = 2 * h + kk;
                        uint32_t en = !(g == 0 && part == 0 && kk == 0);
                        asm volatile("{\n\t.reg .pred p;\n\tsetp.ne.u32 p, %4, 0;\n\t"
                            "tcgen05.mma.cta_group::1.kind::f16 [%0], %1, %2, %3, {%5, %5, %5, %5}, p;\n\t}"
                            :: "r"(dt), "l"(ad + k * 2), "l"(bd + k * 2),
                               "r"(MMA_IDESC), "r"(en), "r"(0u) : "memory");
                    }
                }
            }
            TCGEN05_COMMIT(mbar[h]);
        }
    }

    // ---- wait for the final two halves ----
    {
        int hl = (NHALF - 1) & 1;
        MBARRIER_WAIT_PARITY(mbar[hl], ph[hl]);
        if (NHALF >= 2) MBARRIER_WAIT_PARITY(mbar[1 - hl], ph[1 - hl]);
    }
    TCGEN05_FENCE_AFTER();
    __syncthreads();

    // ---- epilogue: STG + fused BN-stats reduction (A buffer as scratch) ----
    {
        float* scratch = reinterpret_cast<float*>(smem + A_OFF);   // [64 co][132]
        float ssum = 0.f, ssq = 0.f;
        float* obase = out + (size_t)n * CO * HW + (size_t)y * W_;
#pragma unroll
        for (int xblk = 0; xblk < 2; xblk++) {
            if (wid < 4) {
                uint32_t r[64];
                TCGEN05_LD_X32(r,      tmem + xblk * 64);
                TCGEN05_LD_X32(r + 32, tmem + xblk * 64 + 32);
                TCGEN05_WAIT_LD();
                int xl = wid * 32 + lid;
                float* o = obase + xblk * 128 + xl;
#pragma unroll
                for (int cc = 0; cc < 64; cc++) {
                    float v = __uint_as_float(r[cc]);
                    o[(size_t)cc * HW] = v;
                    scratch[cc * 132 + xl] = v;
                }
            }
            __syncthreads();
            if (tid < 64) {
#pragma unroll
                for (int xg = 0; xg < 32; xg++) {
                    float4 v = *reinterpret_cast<float4*>(scratch + tid * 132 + xg * 4);
                    ssum += v.x + v.y + v.z + v.w;
                    ssq  += v.x * v.x + v.y * v.y + v.z * v.z + v.w * v.w;
                }
            }
            __syncthreads();
        }
        if (tid < 64) {
            atomicAdd(&d_psum[tid * N_ + n], ssum);
            atomicAdd(&d_psq [tid * N_ + n], ssq);
        }
    }
    __syncthreads();
    if (tid == 0) { MBARRIER_INVAL(mbar[0]); MBARRIER_INVAL(mbar[1]); }
    __syncthreads();
    if (wid == 0) TCGEN05_DEALLOC(tmem, 128);
#else
    // ================== FFMA2 fallback path (no tcgen05 on this target) ==================
    float* stage = reinterpret_cast<float*>(smem + 1024);      // [5][264]
    float* w_s   = reinterpret_cast<float*>(smem + 8192);      // [25][64]
    int x = tid;                                               // 0..255

    unsigned long long acc[32];
#pragma unroll
    for (int c = 0; c < 32; c++) acc[c] = 0ull;

    for (int ci = 0; ci < CI; ci++) {
        float sc = 1.f, bi = 0.f;
        if (bn) { sc = d_bn[bnLayer][0][ci]; bi = d_bn[bnLayer][1][ci]; }
        const float* inC = inN + (size_t)ci * HW;
        for (int k = tid; k < 5 * 264; k += 256) {
            int c = k % 264, r = k / 264;
            int srcy = y + r - 2, g = c - 2;
            float v = 0.f;
            if ((unsigned)srcy < (unsigned)H_ && (unsigned)g < (unsigned)W_) {
                v = inC[srcy * W_ + g];
                if (bn) v = fmaxf(fmaf(v, sc, bi), 0.f);
            }
            stage[k] = v;
        }
        {
            const float* src = wkf + ((size_t)(n * CI + ci) * 25) * CO;
            for (int k = tid; k < 1600; k += 256) w_s[k] = src[k];
        }
        __syncthreads();
#pragma unroll
        for (int tap = 0; tap < 25; tap++) {
            float iv = stage[(tap / 5) * 264 + x + (tap % 5)];
            unsigned long long IV = pk2(iv, iv);
            const ulonglong2* wp = reinterpret_cast<const ulonglong2*>(w_s + tap * 64);
#pragma unroll
            for (int q = 0; q < 8; q++) {
                ulonglong2 w2 = wp[q];
                fma2(acc[2 * q],     IV, w2.x);
                fma2(acc[2 * q + 1], IV, w2.y);
            }
        }
        __syncthreads();
    }
    {
        float* scratch = reinterpret_cast<float*>(smem + 16384);   // [64 co][260]
        float* obase = out + (size_t)n * CO * HW + (size_t)y * W_ + x;
#pragma unroll
        for (int c = 0; c < 32; c++) {
            float2 v = upk2(acc[c]);
            obase[(size_t)(2 * c) * HW]     = v.x;
            obase[(size_t)(2 * c + 1) * HW] = v.y;
            scratch[(2 * c) * 260 + x]     = v.x;
            scratch[(2 * c + 1) * 260 + x] = v.y;
        }
        __syncthreads();
        if (tid < 64) {
            float ssum = 0.f, ssq = 0.f;
#pragma unroll
            for (int xg = 0; xg < 64; xg++) {
                float4 v = *reinterpret_cast<float4*>(scratch + tid * 260 + xg * 4);
                ssum += v.x + v.y + v.z + v.w;
                ssq  += v.x * v.x + v.y * v.y + v.z * v.z + v.w * v.w;
            }
            atomicAdd(&d_psum[tid * N_ + n], ssum);
            atomicAdd(&d_psq [tid * N_ + n], ssq);
        }
    }
#endif
}

// ================= BN finalize / apply =================
__global__ void finalize_kernel(int layer, const float* __restrict__ gamma,
                                const float* __restrict__ beta) {
    int c = threadIdx.x;
    float s = 0.f, sq = 0.f;
#pragma unroll
    for (int n = 0; n < N_; n++) { s += d_psum[c * N_ + n]; sq += d_psq[c * N_ + n]; }
    const float cnt = (float)(N_ * HW);
    float mean = s / cnt;
    float var  = sq / cnt - mean * mean;
    float rs   = rsqrtf(var + BN_EPS);
    float scale = gamma[c] * rs;
    d_bn[layer][0][c] = scale;
    d_bn[layer][1][c] = beta[c] - mean * scale;
}

__global__ void bn_apply(float* __restrict__ y) {
    size_t i = (size_t)blockIdx.x * blockDim.x + threadIdx.x;
    int c = (int)((i / (HW / 4)) % CO);
    float4* p = (float4*)y;
    float4 v = p[i];
    float scale = d_bn[1][0][c], bias = d_bn[1][1][c];
    v.x = fmaxf(fmaf(v.x, scale, bias), 0.f);
    v.y = fmaxf(fmaf(v.y, scale, bias), 0.f);
    v.z = fmaxf(fmaf(v.z, scale, bias), 0.f);
    v.w = fmaxf(fmaf(v.w, scale, bias), 0.f);
    p[i] = v;
}

// ================= launch =================
extern "C" void kernel_launch(void* const* d_in, const int* in_sizes, int n_in,
                              void* d_out, int out_size) {
    const float* x      = (const float*)d_in[0];
    const float* t      = (const float*)d_in[1];
    const float* w5_1   = (const float*)d_in[2];
    const float* w3_1   = (const float*)d_in[3];
    const float* w1_1   = (const float*)d_in[4];
    const float* a3_1   = (const float*)d_in[5];
    const float* a5_1   = (const float*)d_in[6];
    const float* gw_1   = (const float*)d_in[7];
    const float* gb_1   = (const float*)d_in[8];
    const float* gamma_1= (const float*)d_in[9];
    const float* beta_1 = (const float*)d_in[10];
    const float* w5_2   = (const float*)d_in[11];
    const float* w3_2   = (const float*)d_in[12];
    const float* w1_2   = (const float*)d_in[13];
    const float* a3_2   = (const float*)d_in[14];
    const float* a5_2   = (const float*)d_in[15];
    const float* gw_2   = (const float*)d_in[16];
    const float* gb_2   = (const float*)d_in[17];
    const float* gamma_2= (const float*)d_in[18];
    const float* beta_2 = (const float*)d_in[19];
    float* out = (float*)d_out;

    float* y1; uint8_t *wka1, *wka2; float *wkf1, *wkf2;
    cudaGetSymbolAddress((void**)&y1,   d_y1);
    cudaGetSymbolAddress((void**)&wka1, d_wka1);
    cudaGetSymbolAddress((void**)&wka2, d_wka2);
    cudaGetSymbolAddress((void**)&wkf1, d_wkf1);
    cudaGetSymbolAddress((void**)&wkf2, d_wkf2);

    cudaFuncSetAttribute(conv_mma<CI1>, cudaFuncAttributeMaxDynamicSharedMemorySize, SMEM_SZ);
    cudaFuncSetAttribute(conv_mma<CO>,  cudaFuncAttributeMaxDynamicSharedMemorySize, SMEM_SZ);
    cudaFuncSetAttribute(conv_mma<CI1>, cudaFuncAttributePreferredSharedMemoryCarveout, 100);
    cudaFuncSetAttribute(conv_mma<CO>,  cudaFuncAttributePreferredSharedMemoryCarveout, 100);

    // 1. gates
    gate_kernel<<<2, 512>>>(t, gw_1, gb_1, gw_2, gb_2);

    // 2. per-sample mixed kernels (flat-tau packing + fallback format)
    build_w<<<(N_ * CO * (CI1 / 2) + 255) / 256, 256>>>(0, CI1, NCH1, w5_1, w3_1, w1_1, a3_1, a5_1, wka1, wkf1);
    build_w<<<(N_ * CO * (CO  / 2) + 255) / 256, 256>>>(1, CO,  NCH2, w5_2, w3_2, w1_2, a3_2, a5_2, wka2, wkf2);

    // 3. layer 1: conv (raw, fused stats) -> bn params
    zero_stats<<<1, 512>>>();
    conv_mma<CI1><<<N_ * 256, 256, SMEM_SZ>>>(x, (const uint4*)wka1, wkf1, y1, -1);
    finalize_kernel<<<1, 64>>>(0, gamma_1, beta_1);

    // 4. layer 2: conv (BN1+ReLU fused into stage, fused stats) -> bn -> apply
    zero_stats<<<1, 512>>>();
    conv_mma<CO><<<N_ * 256, 256, SMEM_SZ>>>(y1, (const uint4*)wka2, wkf2, out, 0);
    finalize_kernel<<<1, 64>>>(1, gamma_2, beta_2);
    bn_apply<<<(N_ * CO * HW / 4) / 256, 256>>>(out);
}

// round 14
// speedup vs baseline: 1.2640x; 1.2640x over previous
#include <cuda_runtime.h>
#include <cuda_bf16.h>
#include <math.h>
#include <stdint.h>

#define N_   8
#define CI1  32
#define CO   64
#define T_   8
#define H_   256
#define W_   256
#define HW   (H_*W_)
#define BN_EPS 1e-5f

// flat-tau chunking: tau = pair*25 + tap, chunk c covers tau in [32c, 32c+32)
#define NCH1 13
#define NCH2 25

// ================= device scratch =================
__device__ float d_y1[(size_t)N_ * CO * HW];
__device__ float d_gates[2][N_][5][CO];
// bf16 hi/lo weight tiles: [n][chunk][part(hi,lo)][8KB], row=co(64), col=k(64), SW128
__device__ uint4 d_wka1[(size_t)N_ * NCH1 * 2 * 8192 / 16];
__device__ uint4 d_wka2[(size_t)N_ * NCH2 * 2 * 8192 / 16];
// plain float weights for fallback path: [n][ci][tap][co]
__device__ float d_wkf1[(size_t)N_ * CI1 * 25 * CO];
__device__ float d_wkf2[(size_t)N_ * CO  * 25 * CO];
__device__ float d_psum[CO * N_];
__device__ float d_psq [CO * N_];
__device__ float d_bn[2][2][CO];

// ================= common helpers =================
__device__ __forceinline__ uint32_t smem_u32(const void* p) {
    uint32_t a;
    asm("{ .reg .u64 t; cvta.to.shared.u64 t, %1; cvt.u32.u64 %0, t; }" : "=r"(a) : "l"(p));
    return a;
}
#define SWZ128(o) ((o) ^ (((o) >> 3) & 0x70))

__device__ __forceinline__ unsigned long long pk2(float lo, float hi) {
    unsigned long long r;
    asm("mov.b64 %0, {%1, %2};" : "=l"(r)
        : "r"(__float_as_uint(lo)), "r"(__float_as_uint(hi)));
    return r;
}
__device__ __forceinline__ void fma2(unsigned long long& d,
                                     unsigned long long a, unsigned long long b) {
    asm("fma.rn.f32x2 %0, %1, %2, %0;" : "+l"(d) : "l"(a), "l"(b));
}
__device__ __forceinline__ float2 upk2(unsigned long long v) {
    unsigned int lo, hi;
    asm("mov.b64 {%0, %1}, %2;" : "=r"(lo), "=r"(hi) : "l"(v));
    return make_float2(__uint_as_float(lo), __uint_as_float(hi));
}

// ================= tcgen05 PTX (guarded) =================
#define MBARRIER_INIT(addr, cnt) \
    asm volatile("mbarrier.init.shared.b64 [%0], %1;" :: "r"(addr), "r"(cnt) : "memory")
#define MBARRIER_INVAL(addr) \
    asm volatile("mbarrier.inval.shared.b64 [%0];" :: "r"(addr) : "memory")
#define MBARRIER_WAIT_PARITY(addr, par) do {                                  \
    uint32_t _m = (addr); uint32_t _p = (par); uint32_t _done;                \
    asm volatile("{\n\t.reg .pred p;\n\t"                                     \
        "mbarrier.try_wait.parity.acquire.cta.shared::cta.b64 p, [%1], %2;\n\t" \
        "selp.b32 %0, 1, 0, p;\n\t}"                                          \
        : "=r"(_done) : "r"(_m), "r"(_p) : "memory");                         \
    if (!_done) {                                                             \
        asm volatile("{\n\t.reg .pred P1;\n\t"                                \
            "WL_%=:\n\t"                                                      \
            "mbarrier.try_wait.parity.acquire.cta.shared::cta.b64 P1, [%0], %1, 0x989680;\n\t" \
            "@P1 bra.uni WD_%=;\n\t"                                          \
            "bra.uni WL_%=;\n\t"                                              \
            "WD_%=:\n\t}" :: "r"(_m), "r"(_p) : "memory");                    \
    }                                                                         \
} while (0)

#define TCGEN05_ALLOC(sm, n) \
    asm volatile("tcgen05.alloc.cta_group::1.sync.aligned.shared::cta.b32 [%0], %1;" \
        :: "r"(sm), "r"((uint32_t)(n)) : "memory")
#define TCGEN05_DEALLOC(tm, n) \
    asm volatile("tcgen05.dealloc.cta_group::1.sync.aligned.b32 %0, %1;" :: "r"(tm), "r"((uint32_t)(n)))
#define TCGEN05_RELINQ() \
    asm volatile("tcgen05.relinquish_alloc_permit.cta_group::1.sync.aligned;")
#define TCGEN05_COMMIT(mb) \
    asm volatile("tcgen05.commit.cta_group::1.mbarrier::arrive::one.shared::cluster.b64 [%0];" \
        :: "r"(mb) : "memory")
#define TCGEN05_FENCE_AFTER()  asm volatile("tcgen05.fence::after_thread_sync;" ::: "memory")
#define TCGEN05_WAIT_LD()      asm volatile("tcgen05.wait::ld.sync.aligned;" ::: "memory")
#define FENCE_ASYNC() asm volatile("fence.proxy.async.shared::cta;" ::: "memory")

#define TCGEN05_LD_X32(r, a)                                                  \
    asm volatile("tcgen05.ld.sync.aligned.32x32b.x32.b32 "                    \
        "{%0, %1, %2, %3, %4, %5, %6, %7, %8, %9, %10, %11, %12, %13, %14, %15, " \
        " %16, %17, %18, %19, %20, %21, %22, %23, %24, %25, %26, %27, %28, %29, %30, %31}, [%32];" \
        : "=r"((r)[0]),  "=r"((r)[1]),  "=r"((r)[2]),  "=r"((r)[3]),          \
          "=r"((r)[4]),  "=r"((r)[5]),  "=r"((r)[6]),  "=r"((r)[7]),          \
          "=r"((r)[8]),  "=r"((r)[9]),  "=r"((r)[10]), "=r"((r)[11]),         \
          "=r"((r)[12]), "=r"((r)[13]), "=r"((r)[14]), "=r"((r)[15]),         \
          "=r"((r)[16]), "=r"((r)[17]), "=r"((r)[18]), "=r"((r)[19]),         \
          "=r"((r)[20]), "=r"((r)[21]), "=r"((r)[22]), "=r"((r)[23]),         \
          "=r"((r)[24]), "=r"((r)[25]), "=r"((r)[26]), "=r"((r)[27]),         \
          "=r"((r)[28]), "=r"((r)[29]), "=r"((r)[30]), "=r"((r)[31])          \
        : "r"(a))

// K-major SW128 descriptor (Blackwell version=1): LBO=1, SBO=64
static __device__ __forceinline__ uint64_t desc_k_sw128(uint32_t addr) {
    return ((uint64_t)2 << 61) | ((uint64_t)1 << 46) | ((uint64_t)64 << 32) |
           ((uint64_t)1 << 16) | ((uint64_t)(addr >> 4) & 0x3FFF);
}
// idesc: kind::f16, D=F32(bit4), A=BF16(bit7), B=BF16(bit10), N=64 (8<<17), M=128 (8<<24)
#define MMA_IDESC ((1u << 4) | (1u << 7) | (1u << 10) | (8u << 17) | (8u << 24))

// ================= SMEM layout (tensor path) =================
// ctrl 1KB | stage ring 3 x 1320 uint2 (31680B) | W 16KB | A 64KB = 112 KB, 2 CTAs/SM
#define STG_OFF 1024
#define BW_OFF  32768
#define A_OFF   49152
#define SMEM_SZ 114688

// ================= gates =================
__global__ void gate_kernel(const float* __restrict__ t,
                            const float* __restrict__ gw1, const float* __restrict__ gb1,
                            const float* __restrict__ gw2, const float* __restrict__ gb2) {
    int l = blockIdx.x;
    const float* gw = l ? gw2 : gw1;
    const float* gb = l ? gb2 : gb1;
    int n = threadIdx.x / CO;
    int o = threadIdx.x % CO;
    float tt[T_];
#pragma unroll
    for (int k = 0; k < T_; k++) tt[k] = t[n * T_ + k];
    float lg[5];
    float m = -1e30f;
#pragma unroll
    for (int e = 0; e < 5; e++) {
        int row = e * CO + o;
        float s = gb[row];
#pragma unroll
        for (int k = 0; k < T_; k++) s = fmaf(tt[k], gw[row * T_ + k], s);
        lg[e] = s;
        m = fmaxf(m, s);
    }
    float sum = 0.f;
#pragma unroll
    for (int e = 0; e < 5; e++) { lg[e] = expf(lg[e] - m); sum += lg[e]; }
    float inv = 1.f / sum;
#pragma unroll
    for (int e = 0; e < 5; e++) d_gates[l][n][e][o] = lg[e] * inv;
}

// ================= build per-sample mixed kernels =================
__global__ void build_w(int layer, int Ci, int nchunk,
                        const float* __restrict__ w5, const float* __restrict__ w3,
                        const float* __restrict__ w1, const float* __restrict__ a3,
                        const float* __restrict__ a5,
                        uint8_t* __restrict__ wka, float* __restrict__ wkf) {
    int NPAIR = Ci / 2;
    int idx = blockIdx.x * blockDim.x + threadIdx.x;
    int total = N_ * CO * NPAIR;
    if (idx >= total) return;
    int pair = idx % NPAIR;
    int o = (idx / NPAIR) % CO;
    int n = idx / (NPAIR * CO);
    float g0 = d_gates[layer][n][0][o];
    float g1 = d_gates[layer][n][1][o];
    float g2 = d_gates[layer][n][2][o];
    float g3 = d_gates[layer][n][3][o];
    float g4 = d_gates[layer][n][4][o];
#pragma unroll
    for (int ci_l = 0; ci_l < 2; ci_l++) {
        int i = pair * 2 + ci_l;
        int oi = o * Ci + i;
        for (int tap = 0; tap < 25; tap++) {
            int dy = tap / 5, dx = tap % 5;
            float v = g0 * w5[oi * 25 + tap] + g4 * a5[oi] * (1.f / 125.f);
            if (dy >= 1 && dy <= 3 && dx >= 1 && dx <= 3) {
                v += g1 * w3[oi * 9 + (dy - 1) * 3 + (dx - 1)];
                v += g3 * a3[oi] * (1.f / 27.f);
            }
            if (dy == 2 && dx == 2) v += g2 * w1[oi];
            wkf[(((size_t)(n * Ci + i) * 25 + tap) * CO + o)] = v;

            int tau = pair * 25 + tap;
            int c = tau >> 5;
            int k = (tau & 31) * 2 + ci_l;
            __nv_bfloat16 hi = __float2bfloat16(v);
            float lo_f = v - __bfloat162float(hi);
            __nv_bfloat16 lo = __float2bfloat16(lo_f);
            uint32_t off = SWZ128((uint32_t)(o * 128 + k * 2));
            size_t base = ((size_t)(n * nchunk + c) * 2) * 8192;
            *reinterpret_cast<__nv_bfloat16*>(wka + base + off) = hi;
            *reinterpret_cast<__nv_bfloat16*>(wka + base + 8192 + off) = lo;
        }
    }
}

// ================= zero stats accumulators =================
__global__ void zero_stats() {
    int i = threadIdx.x;
    d_psum[i] = 0.f;
    d_psq[i]  = 0.f;
}

// ================= conv kernel (256 threads, 2 CTAs/SM) =================
template <int CI>
__global__ void __launch_bounds__(256, 2) conv_mma(const float* __restrict__ in,
                                                   const uint4* __restrict__ wka,
                                                   const float* __restrict__ wkf,
                                                   float* __restrict__ out,
                                                   int bnLayer) {
    extern __shared__ char smem[];
    constexpr int NPAIR = CI / 2;
    constexpr int TAU = NPAIR * 25;
    constexpr int NCHUNK = (TAU + 31) / 32;
    constexpr int LASTSTEPS = (TAU - 32 * (NCHUNK - 1) + 7) / 8;
    int tid = threadIdx.x;
    int n = blockIdx.x >> 8;
    int y = blockIdx.x & 255;
    const bool bn = (bnLayer >= 0);
    const float* inN = in + (size_t)n * CI * HW;

#if defined(__CUDA_ARCH_FEAT_SM103_ALL) || defined(__CUDA_ARCH_FEAT_SM100_ALL)
    // ================== tcgen05 tensor-core path ==================
    uint32_t sb = smem_u32(smem);
    int wid = tid >> 5;
    int lid = tid & 31;
    uint32_t mbar = sb + 8;

    if (wid == 0) {
        TCGEN05_ALLOC(sb, 128);
        TCGEN05_RELINQ();          // free permit so twin CTA can allocate
    }
    if (tid == 0) MBARRIER_INIT(mbar, 1);
    __syncthreads();
    uint32_t tmem;
    asm volatile("ld.shared.b32 %0, [%1];" : "=r"(tmem) : "r"(sb));

    const int kg = tid >> 5;            // k-group 0..7
    const int x0 = tid & 31;
    const uint32_t sts_base = SWZ128((uint32_t)(x0 * 128 + kg * 16));

    // ---- stage element offsets (per-thread, pair-invariant) ----
    uint32_t sofs[6];
    uint32_t smask = 0;
#pragma unroll
    for (int i = 0; i < 6; i++) {
        int p = tid + i * 256;
        int c = p % 264, r = p / 264;
        int srcy = y + r - 2, g = c - 2;
        bool v = (p < 1320) && ((unsigned)srcy < (unsigned)H_) && ((unsigned)g < (unsigned)W_);
        sofs[i] = v ? (uint32_t)(srcy * W_ + g) : 0u;
        if (v) smask |= 1u << i;
    }

    uint2* stage = reinterpret_cast<uint2*>(smem + STG_OFF);   // ring: 3 x 1320 uint2 (hi,lo)

    auto loadPair = [&](int q, uint2* u) {
        const float* base = inN + (size_t)q * 2 * HW;
        float s0 = 1.f, b0 = 0.f, s1 = 1.f, b1 = 0.f;
        if (bn) {
            s0 = d_bn[bnLayer][0][2 * q];     b0 = d_bn[bnLayer][1][2 * q];
            s1 = d_bn[bnLayer][0][2 * q + 1]; b1 = d_bn[bnLayer][1][2 * q + 1];
        }
#pragma unroll
        for (int i = 0; i < 6; i++) {
            float va = 0.f, vb = 0.f;
            if (smask >> i & 1) { va = base[sofs[i]]; vb = base[HW + sofs[i]]; }
            if (bn) {
                va = fmaxf(fmaf(va, s0, b0), 0.f);
                vb = fmaxf(fmaf(vb, s1, b1), 0.f);
            }
            uint32_t ua = __float_as_uint(va), ub = __float_as_uint(vb);
            float ha = __uint_as_float(ua & 0xFFFF0000u);
            float hb = __uint_as_float(ub & 0xFFFF0000u);
            u[i].x = __byte_perm(ua, ub, 0x7632);                        // hi pair
            u[i].y = __byte_perm(__float_as_uint(va - ha),
                                 __float_as_uint(vb - hb), 0x7632);      // lo pair
        }
    };
    auto storePair = [&](int q, const uint2* u) {
        uint2* s = stage + (q % 3) * 1320;
#pragma unroll
        for (int i = 0; i < 6; i++) {
            int p = tid + i * 256;
            if (i < 5 || p < 1320) s[p] = u[i];
        }
    };

    // ---- prologue: pairs 0 and 1 into ring slots 0,1 ----
    {
        uint2 u[6];
        loadPair(0, u); storePair(0, u);
        loadPair(1, u); storePair(1, u);
    }
    __syncthreads();

    const uint4* wkN = wka + (size_t)n * NCHUNK * 1024;
    int ph = 0;

    for (int c = 0; c < NCHUNK; c++) {
        // ---- phase 0: prefetch W(c) + next-window stage pairs ----
        const uint4* wsrc = wkN + (size_t)c * 1024;
        uint4 wv[4];
#pragma unroll
        for (int q = 0; q < 4; q++) wv[q] = wsrc[tid + q * 256];

        int phiC = (32 * c + 31) / 25;       if (phiC > NPAIR - 1) phiC = NPAIR - 1;
        int phiN = (32 * c + 63) / 25;       if (phiN > NPAIR - 1) phiN = NPAIR - 1;
        int nNew = (c + 1 < NCHUNK) ? (phiN - phiC) : 0;   // 0..2
        uint2 u0[6], u1[6];
        if (nNew >= 1) loadPair(phiC + 1, u0);
        if (nNew >= 2) loadPair(phiC + 2, u1);

        // ---- phase 1: wait for previous chunk's MMAs (A/W single-buffered) ----
        if (c >= 1) { MBARRIER_WAIT_PARITY(mbar, ph); ph ^= 1; }

        // ---- phase 2a: A-fill from stage ring (LDS.64 loads, no PRMT) ----
        {
            int tau0 = 32 * c + kg * 4;
            if (tau0 < TAU) {
                uint32_t off[4];
#pragma unroll
                for (int j2 = 0; j2 < 4; j2++) {
                    int t = tau0 + j2;
                    int pr = t / 25;
                    int tap = t - 25 * pr;
                    off[j2] = (uint32_t)((pr % 3) * 1320 + (tap / 5) * 264 + x0 + (tap % 5));
                }
                char* Ab = smem + A_OFF;
#pragma unroll
                for (int it = 0; it < 8; it++) {
                    uint2 v0 = stage[off[0] + it * 32];
                    uint2 v1 = stage[off[1] + it * 32];
                    uint2 v2 = stage[off[2] + it * 32];
                    uint2 v3 = stage[off[3] + it * 32];
                    uint32_t so = sts_base + (it & 3) * 4096 + (it >> 2) * 16384;
                    *reinterpret_cast<uint4*>(Ab + so) = make_uint4(v0.x, v1.x, v2.x, v3.x);
                    *reinterpret_cast<uint4*>(Ab + 32768 + so) = make_uint4(v0.y, v1.y, v2.y, v3.y);
                }
            }
        }
        // ---- phase 2b: store weights ----
        {
            uint4* wdst = reinterpret_cast<uint4*>(smem + BW_OFF);
#pragma unroll
            for (int q = 0; q < 4; q++) wdst[tid + q * 256] = wv[q];
        }

        // ---- phase 3: write new stage pairs ----
        // A 32-tau chunk can span up to THREE pairs (all ring slots), so any
        // ring write may collide with this chunk's A-fill reads: always sync
        // before overwriting a slot (R13's conditional sync was a data race).
        if (nNew) {
            __syncthreads();
            storePair(phiC + 1, u0);
            if (nNew >= 2) storePair(phiC + 2, u1);
        }
        FENCE_ASYNC();
        __syncthreads();

        // ---- phase 4: issue MMAs ----
        if (tid == 0) {
            int ksteps = (c == NCHUNK - 1) ? LASTSTEPS : 4;
            uint32_t aBase = sb + A_OFF;
            uint32_t bBase = sb + BW_OFF;
#pragma unroll
            for (int part = 0; part < 3; part++) {
                uint32_t apart = (part == 1) ? 32768u : 0u;   // A lo for part1
                uint32_t bpart = (part == 2) ? 8192u  : 0u;   // B lo for part2
                uint64_t bd = desc_k_sw128(bBase + bpart);
#pragma unroll
                for (int xblk = 0; xblk < 2; xblk++) {
                    uint64_t ad = desc_k_sw128(aBase + apart + xblk * 16384);
                    uint32_t dt = tmem + xblk * 64;
                    for (int k = 0; k < ksteps; k++) {
                        uint32_t en = !(c == 0 && part == 0 && k == 0);
                        asm volatile("{\n\t.reg .pred p;\n\tsetp.ne.u32 p, %4, 0;\n\t"
                            "tcgen05.mma.cta_group::1.kind::f16 [%0], %1, %2, %3, {%5, %5, %5, %5}, p;\n\t}"
                            :: "r"(dt), "l"(ad + k * 2), "l"(bd + k * 2),
                               "r"(MMA_IDESC), "r"(en), "r"(0u) : "memory");
                    }
                }
            }
            TCGEN05_COMMIT(mbar);
        }
    }

    // ---- wait for last chunk ----
    MBARRIER_WAIT_PARITY(mbar, ph);
    TCGEN05_FENCE_AFTER();
    __syncthreads();

    // ---- epilogue: STG + fused BN-stats reduction (A buffer as scratch) ----
    {
        float* scratch = reinterpret_cast<float*>(smem + A_OFF);   // [64 co][132]
        float ssum = 0.f, ssq = 0.f;
        float* obase = out + (size_t)n * CO * HW + (size_t)y * W_;
#pragma unroll
        for (int xblk = 0; xblk < 2; xblk++) {
            if (wid < 4) {
                uint32_t r[64];
                TCGEN05_LD_X32(r,      tmem + xblk * 64);
                TCGEN05_LD_X32(r + 32, tmem + xblk * 64 + 32);
                TCGEN05_WAIT_LD();
                int xl = wid * 32 + lid;
                float* o = obase + xblk * 128 + xl;
#pragma unroll
                for (int cc = 0; cc < 64; cc++) {
                    float v = __uint_as_float(r[cc]);
                    o[(size_t)cc * HW] = v;
                    scratch[cc * 132 + xl] = v;
                }
            }
            __syncthreads();
            if (tid < 64) {
#pragma unroll
                for (int xg = 0; xg < 32; xg++) {
                    float4 v = *reinterpret_cast<float4*>(scratch + tid * 132 + xg * 4);
                    ssum += v.x + v.y + v.z + v.w;
                    ssq  += v.x * v.x + v.y * v.y + v.z * v.z + v.w * v.w;
                }
            }
            __syncthreads();
        }
        if (tid < 64) {
            atomicAdd(&d_psum[tid * N_ + n], ssum);
            atomicAdd(&d_psq [tid * N_ + n], ssq);
        }
    }
    __syncthreads();
    if (tid == 0) MBARRIER_INVAL(mbar);
    __syncthreads();
    if (wid == 0) TCGEN05_DEALLOC(tmem, 128);
#else
    // ================== FFMA2 fallback path (no tcgen05 on this target) ==================
    float* stage = reinterpret_cast<float*>(smem + 1024);      // [5][264]
    float* w_s   = reinterpret_cast<float*>(smem + 8192);      // [25][64]
    int x = tid;                                               // 0..255

    unsigned long long acc[32];
#pragma unroll
    for (int c = 0; c < 32; c++) acc[c] = 0ull;

    for (int ci = 0; ci < CI; ci++) {
        float sc = 1.f, bi = 0.f;
        if (bn) { sc = d_bn[bnLayer][0][ci]; bi = d_bn[bnLayer][1][ci]; }
        const float* inC = inN + (size_t)ci * HW;
        for (int k = tid; k < 5 * 264; k += 256) {
            int c = k % 264, r = k / 264;
            int srcy = y + r - 2, g = c - 2;
            float v = 0.f;
            if ((unsigned)srcy < (unsigned)H_ && (unsigned)g < (unsigned)W_) {
                v = inC[srcy * W_ + g];
                if (bn) v = fmaxf(fmaf(v, sc, bi), 0.f);
            }
            stage[k] = v;
        }
        {
            const float* src = wkf + ((size_t)(n * CI + ci) * 25) * CO;
            for (int k = tid; k < 1600; k += 256) w_s[k] = src[k];
        }
        __syncthreads();
#pragma unroll
        for (int tap = 0; tap < 25; tap++) {
            float iv = stage[(tap / 5) * 264 + x + (tap % 5)];
            unsigned long long IV = pk2(iv, iv);
            const ulonglong2* wp = reinterpret_cast<const ulonglong2*>(w_s + tap * 64);
#pragma unroll
            for (int q = 0; q < 8; q++) {
                ulonglong2 w2 = wp[q];
                fma2(acc[2 * q],     IV, w2.x);
                fma2(acc[2 * q + 1], IV, w2.y);
            }
        }
        __syncthreads();
    }
    {
        float* scratch = reinterpret_cast<float*>(smem + 16384);   // [64 co][260]
        float* obase = out + (size_t)n * CO * HW + (size_t)y * W_ + x;
#pragma unroll
        for (int c = 0; c < 32; c++) {
            float2 v = upk2(acc[c]);
            obase[(size_t)(2 * c) * HW]     = v.x;
            obase[(size_t)(2 * c + 1) * HW] = v.y;
            scratch[(2 * c) * 260 + x]     = v.x;
            scratch[(2 * c + 1) * 260 + x] = v.y;
        }
        __syncthreads();
        if (tid < 64) {
            float ssum = 0.f, ssq = 0.f;
#pragma unroll
            for (int xg = 0; xg < 64; xg++) {
                float4 v = *reinterpret_cast<float4*>(scratch + tid * 260 + xg * 4);
                ssum += v.x + v.y + v.z + v.w;
                ssq  += v.x * v.x + v.y * v.y + v.z * v.z + v.w * v.w;
            }
            atomicAdd(&d_psum[tid * N_ + n], ssum);
            atomicAdd(&d_psq [tid * N_ + n], ssq);
        }
    }
#endif
}

// ================= BN finalize (also re-zeroes accumulators) =================
__global__ void finalize_kernel(int layer, const float* __restrict__ gamma,
                                const float* __restrict__ beta) {
    int c = threadIdx.x;
    float s = 0.f, sq = 0.f;
#pragma unroll
    for (int n = 0; n < N_; n++) { s += d_psum[c * N_ + n]; sq += d_psq[c * N_ + n]; }
#pragma unroll
    for (int n = 0; n < N_; n++) { d_psum[c * N_ + n] = 0.f; d_psq[c * N_ + n] = 0.f; }
    const float cnt = (float)(N_ * HW);
    float mean = s / cnt;
    float var  = sq / cnt - mean * mean;
    float rs   = rsqrtf(var + BN_EPS);
    float scale = gamma[c] * rs;
    d_bn[layer][0][c] = scale;
    d_bn[layer][1][c] = beta[c] - mean * scale;
}

__global__ void bn_apply(float* __restrict__ y) {
    size_t i = (size_t)blockIdx.x * blockDim.x + threadIdx.x;
    int c = (int)((i / (HW / 4)) % CO);
    float4* p = (float4*)y;
    float4 v = p[i];
    float scale = d_bn[1][0][c], bias = d_bn[1][1][c];
    v.x = fmaxf(fmaf(v.x, scale, bias), 0.f);
    v.y = fmaxf(fmaf(v.y, scale, bias), 0.f);
    v.z = fmaxf(fmaf(v.z, scale, bias), 0.f);
    v.w = fmaxf(fmaf(v.w, scale, bias), 0.f);
    p[i] = v;
}

// ================= launch =================
extern "C" void kernel_launch(void* const* d_in, const int* in_sizes, int n_in,
                              void* d_out, int out_size) {
    const float* x      = (const float*)d_in[0];
    const float* t      = (const float*)d_in[1];
    const float* w5_1   = (const float*)d_in[2];
    const float* w3_1   = (const float*)d_in[3];
    const float* w1_1   = (const float*)d_in[4];
    const float* a3_1   = (const float*)d_in[5];
    const float* a5_1   = (const float*)d_in[6];
    const float* gw_1   = (const float*)d_in[7];
    const float* gb_1   = (const float*)d_in[8];
    const float* gamma_1= (const float*)d_in[9];
    const float* beta_1 = (const float*)d_in[10];
    const float* w5_2   = (const float*)d_in[11];
    const float* w3_2   = (const float*)d_in[12];
    const float* w1_2   = (const float*)d_in[13];
    const float* a3_2   = (const float*)d_in[14];
    const float* a5_2   = (const float*)d_in[15];
    const float* gw_2   = (const float*)d_in[16];
    const float* gb_2   = (const float*)d_in[17];
    const float* gamma_2= (const float*)d_in[18];
    const float* beta_2 = (const float*)d_in[19];
    float* out = (float*)d_out;

    float* y1; uint8_t *wka1, *wka2; float *wkf1, *wkf2;
    cudaGetSymbolAddress((void**)&y1,   d_y1);
    cudaGetSymbolAddress((void**)&wka1, d_wka1);
    cudaGetSymbolAddress((void**)&wka2, d_wka2);
    cudaGetSymbolAddress((void**)&wkf1, d_wkf1);
    cudaGetSymbolAddress((void**)&wkf2, d_wkf2);

    cudaFuncSetAttribute(conv_mma<CI1>, cudaFuncAttributeMaxDynamicSharedMemorySize, SMEM_SZ);
    cudaFuncSetAttribute(conv_mma<CO>,  cudaFuncAttributeMaxDynamicSharedMemorySize, SMEM_SZ);
    cudaFuncSetAttribute(conv_mma<CI1>, cudaFuncAttributePreferredSharedMemoryCarveout, 100);
    cudaFuncSetAttribute(conv_mma<CO>,  cudaFuncAttributePreferredSharedMemoryCarveout, 100);

    // 1. gates + initial stats zero
    gate_kernel<<<2, 512>>>(t, gw_1, gb_1, gw_2, gb_2);
    zero_stats<<<1, 512>>>();

    // 2. per-sample mixed kernels (flat-tau packing + fallback format)
    build_w<<<(N_ * CO * (CI1 / 2) + 255) / 256, 256>>>(0, CI1, NCH1, w5_1, w3_1, w1_1, a3_1, a5_1, wka1, wkf1);
    build_w<<<(N_ * CO * (CO  / 2) + 255) / 256, 256>>>(1, CO,  NCH2, w5_2, w3_2, w1_2, a3_2, a5_2, wka2, wkf2);

    // 3. layer 1: conv (raw, fused stats) -> bn params (finalize re-zeroes stats)
    conv_mma<CI1><<<N_ * 256, 256, SMEM_SZ>>>(x, (const uint4*)wka1, wkf1, y1, -1);
    finalize_kernel<<<1, 64>>>(0, gamma_1, beta_1);

    // 4. layer 2: conv (BN1+ReLU fused into stage, fused stats) -> bn -> apply
    conv_mma<CO><<<N_ * 256, 256, SMEM_SZ>>>(y1, (const uint4*)wka2, wkf2, out, 0);
    finalize_kernel<<<1, 64>>>(1, gamma_2, beta_2);
    bn_apply<<<(N_ * CO * HW / 4) / 256, 256>>>(out);
}

// round 15
// speedup vs baseline: 1.3332x; 1.0548x over previous
#include <cuda_runtime.h>
#include <cuda_bf16.h>
#include <math.h>
#include <stdint.h>

#define N_   8
#define CI1  32
#define CO   64
#define T_   8
#define H_   256
#define W_   256
#define HW   (H_*W_)
#define BN_EPS 1e-5f

// flat-tau chunking: tau = pair*25 + tap, chunk c covers tau in [32c, 32c+32)
#define NCH1 13
#define NCH2 25

// ================= device scratch =================
__device__ float d_y1[(size_t)N_ * CO * HW];
__device__ float d_gates[2][N_][5][CO];
// bf16 hi/lo weight tiles: [n][chunk][part(hi,lo)][8KB], row=co(64), col=k(64), SW128
__device__ uint4 d_wka1[(size_t)N_ * NCH1 * 2 * 8192 / 16];
__device__ uint4 d_wka2[(size_t)N_ * NCH2 * 2 * 8192 / 16];
// plain float weights for fallback path: [n][ci][tap][co]
__device__ float d_wkf1[(size_t)N_ * CI1 * 25 * CO];
__device__ float d_wkf2[(size_t)N_ * CO  * 25 * CO];
__device__ float d_psum[CO * N_];
__device__ float d_psq [CO * N_];
__device__ float d_bn[2][2][CO];

// ================= common helpers =================
__device__ __forceinline__ uint32_t smem_u32(const void* p) {
    uint32_t a;
    asm("{ .reg .u64 t; cvta.to.shared.u64 t, %1; cvt.u32.u64 %0, t; }" : "=r"(a) : "l"(p));
    return a;
}
#define SWZ128(o) ((o) ^ (((o) >> 3) & 0x70))

__device__ __forceinline__ unsigned long long pk2(float lo, float hi) {
    unsigned long long r;
    asm("mov.b64 %0, {%1, %2};" : "=l"(r)
        : "r"(__float_as_uint(lo)), "r"(__float_as_uint(hi)));
    return r;
}
__device__ __forceinline__ void fma2(unsigned long long& d,
                                     unsigned long long a, unsigned long long b) {
    asm("fma.rn.f32x2 %0, %1, %2, %0;" : "+l"(d) : "l"(a), "l"(b));
}
__device__ __forceinline__ float2 upk2(unsigned long long v) {
    unsigned int lo, hi;
    asm("mov.b64 {%0, %1}, %2;" : "=r"(lo), "=r"(hi) : "l"(v));
    return make_float2(__uint_as_float(lo), __uint_as_float(hi));
}

// ================= tcgen05 PTX (guarded) =================
#define MBARRIER_INIT(addr, cnt) \
    asm volatile("mbarrier.init.shared.b64 [%0], %1;" :: "r"(addr), "r"(cnt) : "memory")
#define MBARRIER_INVAL(addr) \
    asm volatile("mbarrier.inval.shared.b64 [%0];" :: "r"(addr) : "memory")
#define MBARRIER_WAIT_PARITY(addr, par) do {                                  \
    uint32_t _m = (addr); uint32_t _p = (par); uint32_t _done;                \
    asm volatile("{\n\t.reg .pred p;\n\t"                                     \
        "mbarrier.try_wait.parity.acquire.cta.shared::cta.b64 p, [%1], %2;\n\t" \
        "selp.b32 %0, 1, 0, p;\n\t}"                                          \
        : "=r"(_done) : "r"(_m), "r"(_p) : "memory");                         \
    if (!_done) {                                                             \
        asm volatile("{\n\t.reg .pred P1;\n\t"                                \
            "WL_%=:\n\t"                                                      \
            "mbarrier.try_wait.parity.acquire.cta.shared::cta.b64 P1, [%0], %1, 0x989680;\n\t" \
            "@P1 bra.uni WD_%=;\n\t"                                          \
            "bra.uni WL_%=;\n\t"                                              \
            "WD_%=:\n\t}" :: "r"(_m), "r"(_p) : "memory");                    \
    }                                                                         \
} while (0)

#define TCGEN05_ALLOC(sm, n) \
    asm volatile("tcgen05.alloc.cta_group::1.sync.aligned.shared::cta.b32 [%0], %1;" \
        :: "r"(sm), "r"((uint32_t)(n)) : "memory")
#define TCGEN05_DEALLOC(tm, n) \
    asm volatile("tcgen05.dealloc.cta_group::1.sync.aligned.b32 %0, %1;" :: "r"(tm), "r"((uint32_t)(n)))
#define TCGEN05_RELINQ() \
    asm volatile("tcgen05.relinquish_alloc_permit.cta_group::1.sync.aligned;")
#define TCGEN05_COMMIT(mb) \
    asm volatile("tcgen05.commit.cta_group::1.mbarrier::arrive::one.shared::cluster.b64 [%0];" \
        :: "r"(mb) : "memory")
#define TCGEN05_FENCE_AFTER()  asm volatile("tcgen05.fence::after_thread_sync;" ::: "memory")
#define TCGEN05_WAIT_LD()      asm volatile("tcgen05.wait::ld.sync.aligned;" ::: "memory")
#define FENCE_ASYNC() asm volatile("fence.proxy.async.shared::cta;" ::: "memory")

#define TCGEN05_LD_X32(r, a)                                                  \
    asm volatile("tcgen05.ld.sync.aligned.32x32b.x32.b32 "                    \
        "{%0, %1, %2, %3, %4, %5, %6, %7, %8, %9, %10, %11, %12, %13, %14, %15, " \
        " %16, %17, %18, %19, %20, %21, %22, %23, %24, %25, %26, %27, %28, %29, %30, %31}, [%32];" \
        : "=r"((r)[0]),  "=r"((r)[1]),  "=r"((r)[2]),  "=r"((r)[3]),          \
          "=r"((r)[4]),  "=r"((r)[5]),  "=r"((r)[6]),  "=r"((r)[7]),          \
          "=r"((r)[8]),  "=r"((r)[9]),  "=r"((r)[10]), "=r"((r)[11]),         \
          "=r"((r)[12]), "=r"((r)[13]), "=r"((r)[14]), "=r"((r)[15]),         \
          "=r"((r)[16]), "=r"((r)[17]), "=r"((r)[18]), "=r"((r)[19]),         \
          "=r"((r)[20]), "=r"((r)[21]), "=r"((r)[22]), "=r"((r)[23]),         \
          "=r"((r)[24]), "=r"((r)[25]), "=r"((r)[26]), "=r"((r)[27]),         \
          "=r"((r)[28]), "=r"((r)[29]), "=r"((r)[30]), "=r"((r)[31])          \
        : "r"(a))

// K-major SW128 descriptor (Blackwell version=1): LBO=1, SBO=64
static __device__ __forceinline__ uint64_t desc_k_sw128(uint32_t addr) {
    return ((uint64_t)2 << 61) | ((uint64_t)1 << 46) | ((uint64_t)64 << 32) |
           ((uint64_t)1 << 16) | ((uint64_t)(addr >> 4) & 0x3FFF);
}
// idesc: kind::f16, D=F32(bit4), A=BF16(bit7), B=BF16(bit10), N=64 (8<<17), M=128 (8<<24)
#define MMA_IDESC ((1u << 4) | (1u << 7) | (1u << 10) | (8u << 17) | (8u << 24))

// ================= SMEM layout (tensor path) =================
// ctrl 1KB | stage ring 3 x 1320 uint2 (31680B) | W 16KB | A 64KB = 112 KB, 2 CTAs/SM
#define STG_OFF 1024
#define BW_OFF  32768
#define A_OFF   49152
#define SMEM_SZ 114688

// ================= gates =================
__global__ void gate_kernel(const float* __restrict__ t,
                            const float* __restrict__ gw1, const float* __restrict__ gb1,
                            const float* __restrict__ gw2, const float* __restrict__ gb2) {
    int l = blockIdx.x;
    const float* gw = l ? gw2 : gw1;
    const float* gb = l ? gb2 : gb1;
    int n = threadIdx.x / CO;
    int o = threadIdx.x % CO;
    float tt[T_];
#pragma unroll
    for (int k = 0; k < T_; k++) tt[k] = t[n * T_ + k];
    float lg[5];
    float m = -1e30f;
#pragma unroll
    for (int e = 0; e < 5; e++) {
        int row = e * CO + o;
        float s = gb[row];
#pragma unroll
        for (int k = 0; k < T_; k++) s = fmaf(tt[k], gw[row * T_ + k], s);
        lg[e] = s;
        m = fmaxf(m, s);
    }
    float sum = 0.f;
#pragma unroll
    for (int e = 0; e < 5; e++) { lg[e] = expf(lg[e] - m); sum += lg[e]; }
    float inv = 1.f / sum;
#pragma unroll
    for (int e = 0; e < 5; e++) d_gates[l][n][e][o] = lg[e] * inv;
}

// ================= build per-sample mixed kernels =================
// One thread per (n, o, tau). Computes both ci values of the tap (k = kslot*2
// and kslot*2+1 share one aligned u32 in the SW128 tile) -> 1 u32 store for hi
// and 1 for lo instead of 4 scattered bf16 stores.
__global__ void build_w(int layer, int Ci, int nchunk,
                        const float* __restrict__ w5, const float* __restrict__ w3,
                        const float* __restrict__ w1, const float* __restrict__ a3,
                        const float* __restrict__ a5,
                        uint8_t* __restrict__ wka, float* __restrict__ wkf) {
    int TAUL = (Ci / 2) * 25;
    int idx = blockIdx.x * blockDim.x + threadIdx.x;
    int total = N_ * CO * TAUL;
    if (idx >= total) return;
    int tau = idx % TAUL;
    int o = (idx / TAUL) % CO;
    int n = idx / (TAUL * CO);
    int pair = tau / 25, tap = tau - 25 * pair;
    int dy = tap / 5, dx = tap % 5;
    bool inner = (dy >= 1 && dy <= 3 && dx >= 1 && dx <= 3);
    bool center = (dy == 2 && dx == 2);
    float g0 = d_gates[layer][n][0][o];
    float g1 = d_gates[layer][n][1][o];
    float g2 = d_gates[layer][n][2][o];
    float g3 = d_gates[layer][n][3][o];
    float g4 = d_gates[layer][n][4][o];

    float v[2];
#pragma unroll
    for (int ci_l = 0; ci_l < 2; ci_l++) {
        int i = pair * 2 + ci_l;
        int oi = o * Ci + i;
        float t0 = g0 * w5[oi * 25 + tap] + g4 * a5[oi] * (1.f / 125.f);
        if (inner) {
            t0 += g1 * w3[oi * 9 + (dy - 1) * 3 + (dx - 1)];
            t0 += g3 * a3[oi] * (1.f / 27.f);
        }
        if (center) t0 += g2 * w1[oi];
        v[ci_l] = t0;
        wkf[(((size_t)(n * Ci + i) * 25 + tap) * CO + o)] = t0;
    }

    int c = tau >> 5;
    int kslot = tau & 31;
    // pack (ci0, ci1) bf16 pair: lo halfword = ci0, hi halfword = ci1
    uint32_t u0 = __float_as_uint(v[0]), u1 = __float_as_uint(v[1]);
    float h0 = __uint_as_float(u0 & 0xFFFF0000u);
    float h1 = __uint_as_float(u1 & 0xFFFF0000u);
    uint32_t hiP = __byte_perm(u0, u1, 0x7632);
    uint32_t loP = __byte_perm(__float_as_uint(v[0] - h0),
                               __float_as_uint(v[1] - h1), 0x7632);
    uint32_t off = SWZ128((uint32_t)(o * 128 + kslot * 4));
    size_t base = ((size_t)(n * nchunk + c) * 2) * 8192;
    *reinterpret_cast<uint32_t*>(wka + base + off) = hiP;
    *reinterpret_cast<uint32_t*>(wka + base + 8192 + off) = loP;
}

// ================= zero stats accumulators =================
__global__ void zero_stats() {
    int i = threadIdx.x;
    d_psum[i] = 0.f;
    d_psq[i]  = 0.f;
}

// ================= conv kernel (256 threads, 2 CTAs/SM) =================
template <int CI>
__global__ void __launch_bounds__(256, 2) conv_mma(const float* __restrict__ in,
                                                   const uint4* __restrict__ wka,
                                                   const float* __restrict__ wkf,
                                                   float* __restrict__ out,
                                                   int bnLayer) {
    extern __shared__ char smem[];
    constexpr int NPAIR = CI / 2;
    constexpr int TAU = NPAIR * 25;
    constexpr int NCHUNK = (TAU + 31) / 32;
    constexpr int LASTSTEPS = (TAU - 32 * (NCHUNK - 1) + 7) / 8;
    int tid = threadIdx.x;
    int n = blockIdx.x >> 8;
    int y = blockIdx.x & 255;
    const bool bn = (bnLayer >= 0);
    const float* inN = in + (size_t)n * CI * HW;

#if defined(__CUDA_ARCH_FEAT_SM103_ALL) || defined(__CUDA_ARCH_FEAT_SM100_ALL)
    // ================== tcgen05 tensor-core path ==================
    uint32_t sb = smem_u32(smem);
    int wid = tid >> 5;
    int lid = tid & 31;
    uint32_t mbar = sb + 8;

    if (wid == 0) {
        TCGEN05_ALLOC(sb, 128);
        TCGEN05_RELINQ();          // free permit so twin CTA can allocate
    }
    if (tid == 0) MBARRIER_INIT(mbar, 1);
    __syncthreads();
    uint32_t tmem;
    asm volatile("ld.shared.b32 %0, [%1];" : "=r"(tmem) : "r"(sb));

    const int kg = tid >> 5;            // k-group 0..7
    const int x0 = tid & 31;
    const uint32_t sts_base = SWZ128((uint32_t)(x0 * 128 + kg * 16));

    // ---- stage element offsets (per-thread, pair-invariant) ----
    uint32_t sofs[6];
    uint32_t smask = 0;
#pragma unroll
    for (int i = 0; i < 6; i++) {
        int p = tid + i * 256;
        int c = p % 264, r = p / 264;
        int srcy = y + r - 2, g = c - 2;
        bool v = (p < 1320) && ((unsigned)srcy < (unsigned)H_) && ((unsigned)g < (unsigned)W_);
        sofs[i] = v ? (uint32_t)(srcy * W_ + g) : 0u;
        if (v) smask |= 1u << i;
    }

    uint2* stage = reinterpret_cast<uint2*>(smem + STG_OFF);   // ring: 3 x 1320 uint2 (hi,lo)

    auto loadPair = [&](int q, uint2* u) {
        const float* base = inN + (size_t)q * 2 * HW;
        float s0 = 1.f, b0 = 0.f, s1 = 1.f, b1 = 0.f;
        if (bn) {
            s0 = d_bn[bnLayer][0][2 * q];     b0 = d_bn[bnLayer][1][2 * q];
            s1 = d_bn[bnLayer][0][2 * q + 1]; b1 = d_bn[bnLayer][1][2 * q + 1];
        }
#pragma unroll
        for (int i = 0; i < 6; i++) {
            float va = 0.f, vb = 0.f;
            if (smask >> i & 1) { va = base[sofs[i]]; vb = base[HW + sofs[i]]; }
            if (bn) {
                va = fmaxf(fmaf(va, s0, b0), 0.f);
                vb = fmaxf(fmaf(vb, s1, b1), 0.f);
            }
            uint32_t ua = __float_as_uint(va), ub = __float_as_uint(vb);
            float ha = __uint_as_float(ua & 0xFFFF0000u);
            float hb = __uint_as_float(ub & 0xFFFF0000u);
            u[i].x = __byte_perm(ua, ub, 0x7632);                        // hi pair
            u[i].y = __byte_perm(__float_as_uint(va - ha),
                                 __float_as_uint(vb - hb), 0x7632);      // lo pair
        }
    };
    auto storePair = [&](int q, const uint2* u) {
        uint2* s = stage + (q % 3) * 1320;
#pragma unroll
        for (int i = 0; i < 6; i++) {
            int p = tid + i * 256;
            if (i < 5 || p < 1320) s[p] = u[i];
        }
    };

    // ---- prologue: pairs 0 and 1 into ring slots 0,1 ----
    {
        uint2 u[6];
        loadPair(0, u); storePair(0, u);
        loadPair(1, u); storePair(1, u);
    }
    __syncthreads();

    const uint4* wkN = wka + (size_t)n * NCHUNK * 1024;
    int ph = 0;

    for (int c = 0; c < NCHUNK; c++) {
        // ---- phase 0: prefetch W(c) + next-window stage pairs ----
        const uint4* wsrc = wkN + (size_t)c * 1024;
        uint4 wv[4];
#pragma unroll
        for (int q = 0; q < 4; q++) wv[q] = wsrc[tid + q * 256];

        int phiC = (32 * c + 31) / 25;       if (phiC > NPAIR - 1) phiC = NPAIR - 1;
        int phiN = (32 * c + 63) / 25;       if (phiN > NPAIR - 1) phiN = NPAIR - 1;
        int nNew = (c + 1 < NCHUNK) ? (phiN - phiC) : 0;   // 0..2
        uint2 u0[6], u1[6];
        if (nNew >= 1) loadPair(phiC + 1, u0);
        if (nNew >= 2) loadPair(phiC + 2, u1);

        // ---- phase 1: wait for previous chunk's MMAs (A/W single-buffered) ----
        if (c >= 1) { MBARRIER_WAIT_PARITY(mbar, ph); ph ^= 1; }

        // ---- phase 2a: A-fill from stage ring (LDS.64 loads, no PRMT) ----
        {
            int tau0 = 32 * c + kg * 4;
            if (tau0 < TAU) {
                uint32_t off[4];
#pragma unroll
                for (int j2 = 0; j2 < 4; j2++) {
                    int t = tau0 + j2;
                    int pr = t / 25;
                    int tap = t - 25 * pr;
                    off[j2] = (uint32_t)((pr % 3) * 1320 + (tap / 5) * 264 + x0 + (tap % 5));
                }
                char* Ab = smem + A_OFF;
#pragma unroll
                for (int it = 0; it < 8; it++) {
                    uint2 v0 = stage[off[0] + it * 32];
                    uint2 v1 = stage[off[1] + it * 32];
                    uint2 v2 = stage[off[2] + it * 32];
                    uint2 v3 = stage[off[3] + it * 32];
                    uint32_t so = sts_base + (it & 3) * 4096 + (it >> 2) * 16384;
                    *reinterpret_cast<uint4*>(Ab + so) = make_uint4(v0.x, v1.x, v2.x, v3.x);
                    *reinterpret_cast<uint4*>(Ab + 32768 + so) = make_uint4(v0.y, v1.y, v2.y, v3.y);
                }
            }
        }
        // ---- phase 2b: store weights ----
        {
            uint4* wdst = reinterpret_cast<uint4*>(smem + BW_OFF);
#pragma unroll
            for (int q = 0; q < 4; q++) wdst[tid + q * 256] = wv[q];
        }

        // ---- phase 3: write new stage pairs ----
        // A 32-tau chunk can span up to THREE pairs (all ring slots), so any
        // ring write may collide with this chunk's A-fill reads: always sync
        // before overwriting a slot.
        if (nNew) {
            __syncthreads();
            storePair(phiC + 1, u0);
            if (nNew >= 2) storePair(phiC + 2, u1);
        }
        FENCE_ASYNC();
        __syncthreads();

        // ---- phase 4: issue MMAs ----
        if (tid == 0) {
            int ksteps = (c == NCHUNK - 1) ? LASTSTEPS : 4;
            uint32_t aBase = sb + A_OFF;
            uint32_t bBase = sb + BW_OFF;
#pragma unroll
            for (int part = 0; part < 3; part++) {
                uint32_t apart = (part == 1) ? 32768u : 0u;   // A lo for part1
                uint32_t bpart = (part == 2) ? 8192u  : 0u;   // B lo for part2
                uint64_t bd = desc_k_sw128(bBase + bpart);
#pragma unroll
                for (int xblk = 0; xblk < 2; xblk++) {
                    uint64_t ad = desc_k_sw128(aBase + apart + xblk * 16384);
                    uint32_t dt = tmem + xblk * 64;
                    for (int k = 0; k < ksteps; k++) {
                        uint32_t en = !(c == 0 && part == 0 && k == 0);
                        asm volatile("{\n\t.reg .pred p;\n\tsetp.ne.u32 p, %4, 0;\n\t"
                            "tcgen05.mma.cta_group::1.kind::f16 [%0], %1, %2, %3, {%5, %5, %5, %5}, p;\n\t}"
                            :: "r"(dt), "l"(ad + k * 2), "l"(bd + k * 2),
                               "r"(MMA_IDESC), "r"(en), "r"(0u) : "memory");
                    }
                }
            }
            TCGEN05_COMMIT(mbar);
        }
    }

    // ---- wait for last chunk ----
    MBARRIER_WAIT_PARITY(mbar, ph);
    TCGEN05_FENCE_AFTER();
    __syncthreads();

    // ---- epilogue: STG + fused BN-stats reduction (A buffer as scratch) ----
    {
        float* scratch = reinterpret_cast<float*>(smem + A_OFF);   // [64 co][132]
        float ssum = 0.f, ssq = 0.f;
        float* obase = out + (size_t)n * CO * HW + (size_t)y * W_;
#pragma unroll
        for (int xblk = 0; xblk < 2; xblk++) {
            if (wid < 4) {
                uint32_t r[64];
                TCGEN05_LD_X32(r,      tmem + xblk * 64);
                TCGEN05_LD_X32(r + 32, tmem + xblk * 64 + 32);
                TCGEN05_WAIT_LD();
                int xl = wid * 32 + lid;
                float* o = obase + xblk * 128 + xl;
#pragma unroll
                for (int cc = 0; cc < 64; cc++) {
                    float v = __uint_as_float(r[cc]);
                    o[(size_t)cc * HW] = v;
                    scratch[cc * 132 + xl] = v;
                }
            }
            __syncthreads();
            if (tid < 64) {
#pragma unroll
                for (int xg = 0; xg < 32; xg++) {
                    float4 v = *reinterpret_cast<float4*>(scratch + tid * 132 + xg * 4);
                    ssum += v.x + v.y + v.z + v.w;
                    ssq  += v.x * v.x + v.y * v.y + v.z * v.z + v.w * v.w;
                }
            }
            __syncthreads();
        }
        if (tid < 64) {
            atomicAdd(&d_psum[tid * N_ + n], ssum);
            atomicAdd(&d_psq [tid * N_ + n], ssq);
        }
    }
    __syncthreads();
    if (tid == 0) MBARRIER_INVAL(mbar);
    __syncthreads();
    if (wid == 0) TCGEN05_DEALLOC(tmem, 128);
#else
    // ================== FFMA2 fallback path (no tcgen05 on this target) ==================
    float* stage = reinterpret_cast<float*>(smem + 1024);      // [5][264]
    float* w_s   = reinterpret_cast<float*>(smem + 8192);      // [25][64]
    int x = tid;                                               // 0..255

    unsigned long long acc[32];
#pragma unroll
    for (int c = 0; c < 32; c++) acc[c] = 0ull;

    for (int ci = 0; ci < CI; ci++) {
        float sc = 1.f, bi = 0.f;
        if (bn) { sc = d_bn[bnLayer][0][ci]; bi = d_bn[bnLayer][1][ci]; }
        const float* inC = inN + (size_t)ci * HW;
        for (int k = tid; k < 5 * 264; k += 256) {
            int c = k % 264, r = k / 264;
            int srcy = y + r - 2, g = c - 2;
            float v = 0.f;
            if ((unsigned)srcy < (unsigned)H_ && (unsigned)g < (unsigned)W_) {
                v = inC[srcy * W_ + g];
                if (bn) v = fmaxf(fmaf(v, sc, bi), 0.f);
            }
            stage[k] = v;
        }
        {
            const float* src = wkf + ((size_t)(n * CI + ci) * 25) * CO;
            for (int k = tid; k < 1600; k += 256) w_s[k] = src[k];
        }
        __syncthreads();
#pragma unroll
        for (int tap = 0; tap < 25; tap++) {
            float iv = stage[(tap / 5) * 264 + x + (tap % 5)];
            unsigned long long IV = pk2(iv, iv);
            const ulonglong2* wp = reinterpret_cast<const ulonglong2*>(w_s + tap * 64);
#pragma unroll
            for (int q = 0; q < 8; q++) {
                ulonglong2 w2 = wp[q];
                fma2(acc[2 * q],     IV, w2.x);
                fma2(acc[2 * q + 1], IV, w2.y);
            }
        }
        __syncthreads();
    }
    {
        float* scratch = reinterpret_cast<float*>(smem + 16384);   // [64 co][260]
        float* obase = out + (size_t)n * CO * HW + (size_t)y * W_ + x;
#pragma unroll
        for (int c = 0; c < 32; c++) {
            float2 v = upk2(acc[c]);
            obase[(size_t)(2 * c) * HW]     = v.x;
            obase[(size_t)(2 * c + 1) * HW] = v.y;
            scratch[(2 * c) * 260 + x]     = v.x;
            scratch[(2 * c + 1) * 260 + x] = v.y;
        }
        __syncthreads();
        if (tid < 64) {
            float ssum = 0.f, ssq = 0.f;
#pragma unroll
            for (int xg = 0; xg < 64; xg++) {
                float4 v = *reinterpret_cast<float4*>(scratch + tid * 260 + xg * 4);
                ssum += v.x + v.y + v.z + v.w;
                ssq  += v.x * v.x + v.y * v.y + v.z * v.z + v.w * v.w;
            }
            atomicAdd(&d_psum[tid * N_ + n], ssum);
            atomicAdd(&d_psq [tid * N_ + n], ssq);
        }
    }
#endif
}

// ================= BN finalize (also re-zeroes accumulators) =================
__global__ void finalize_kernel(int layer, const float* __restrict__ gamma,
                                const float* __restrict__ beta) {
    int c = threadIdx.x;
    float s = 0.f, sq = 0.f;
#pragma unroll
    for (int n = 0; n < N_; n++) { s += d_psum[c * N_ + n]; sq += d_psq[c * N_ + n]; }
#pragma unroll
    for (int n = 0; n < N_; n++) { d_psum[c * N_ + n] = 0.f; d_psq[c * N_ + n] = 0.f; }
    const float cnt = (float)(N_ * HW);
    float mean = s / cnt;
    float var  = sq / cnt - mean * mean;
    float rs   = rsqrtf(var + BN_EPS);
    float scale = gamma[c] * rs;
    d_bn[layer][0][c] = scale;
    d_bn[layer][1][c] = beta[c] - mean * scale;
}

__global__ void bn_apply(float* __restrict__ y) {
    size_t i = (size_t)blockIdx.x * blockDim.x + threadIdx.x;
    int c = (int)((i / (HW / 4)) % CO);
    float4* p = (float4*)y;
    float4 v = p[i];
    float scale = d_bn[1][0][c], bias = d_bn[1][1][c];
    v.x = fmaxf(fmaf(v.x, scale, bias), 0.f);
    v.y = fmaxf(fmaf(v.y, scale, bias), 0.f);
    v.z = fmaxf(fmaf(v.z, scale, bias), 0.f);
    v.w = fmaxf(fmaf(v.w, scale, bias), 0.f);
    p[i] = v;
}

// ================= launch =================
extern "C" void kernel_launch(void* const* d_in, const int* in_sizes, int n_in,
                              void* d_out, int out_size) {
    const float* x      = (const float*)d_in[0];
    const float* t      = (const float*)d_in[1];
    const float* w5_1   = (const float*)d_in[2];
    const float* w3_1   = (const float*)d_in[3];
    const float* w1_1   = (const float*)d_in[4];
    const float* a3_1   = (const float*)d_in[5];
    const float* a5_1   = (const float*)d_in[6];
    const float* gw_1   = (const float*)d_in[7];
    const float* gb_1   = (const float*)d_in[8];
    const float* gamma_1= (const float*)d_in[9];
    const float* beta_1 = (const float*)d_in[10];
    const float* w5_2   = (const float*)d_in[11];
    const float* w3_2   = (const float*)d_in[12];
    const float* w1_2   = (const float*)d_in[13];
    const float* a3_2   = (const float*)d_in[14];
    const float* a5_2   = (const float*)d_in[15];
    const float* gw_2   = (const float*)d_in[16];
    const float* gb_2   = (const float*)d_in[17];
    const float* gamma_2= (const float*)d_in[18];
    const float* beta_2 = (const float*)d_in[19];
    float* out = (float*)d_out;

    float* y1; uint8_t *wka1, *wka2; float *wkf1, *wkf2;
    cudaGetSymbolAddress((void**)&y1,   d_y1);
    cudaGetSymbolAddress((void**)&wka1, d_wka1);
    cudaGetSymbolAddress((void**)&wka2, d_wka2);
    cudaGetSymbolAddress((void**)&wkf1, d_wkf1);
    cudaGetSymbolAddress((void**)&wkf2, d_wkf2);

    cudaFuncSetAttribute(conv_mma<CI1>, cudaFuncAttributeMaxDynamicSharedMemorySize, SMEM_SZ);
    cudaFuncSetAttribute(conv_mma<CO>,  cudaFuncAttributeMaxDynamicSharedMemorySize, SMEM_SZ);
    cudaFuncSetAttribute(conv_mma<CI1>, cudaFuncAttributePreferredSharedMemoryCarveout, 100);
    cudaFuncSetAttribute(conv_mma<CO>,  cudaFuncAttributePreferredSharedMemoryCarveout, 100);

    // 1. gates + initial stats zero
    gate_kernel<<<2, 512>>>(t, gw_1, gb_1, gw_2, gb_2);
    zero_stats<<<1, 512>>>();

    // 2. per-sample mixed kernels (one thread per (n,o,tau))
    build_w<<<(N_ * CO * ((CI1 / 2) * 25) + 255) / 256, 256>>>(0, CI1, NCH1, w5_1, w3_1, w1_1, a3_1, a5_1, wka1, wkf1);
    build_w<<<(N_ * CO * ((CO  / 2) * 25) + 255) / 256, 256>>>(1, CO,  NCH2, w5_2, w3_2, w1_2, a3_2, a5_2, wka2, wkf2);

    // 3. layer 1: conv (raw, fused stats) -> bn params (finalize re-zeroes stats)
    conv_mma<CI1><<<N_ * 256, 256, SMEM_SZ>>>(x, (const uint4*)wka1, wkf1, y1, -1);
    finalize_kernel<<<1, 64>>>(0, gamma_1, beta_1);

    // 4. layer 2: conv (BN1+ReLU fused into stage, fused stats) -> bn -> apply
    conv_mma<CO><<<N_ * 256, 256, SMEM_SZ>>>(y1, (const uint4*)wka2, wkf2, out, 0);
    finalize_kernel<<<1, 64>>>(1, gamma_2, beta_2);
    bn_apply<<<(N_ * CO * HW / 4) / 256, 256>>>(out);
}